// round 3
// baseline (speedup 1.0000x reference)
#include <cuda_runtime.h>

// Dynamic 5x5 per-pixel convolution + leaky_relu(0.2), replicate padding.
// x:      (N, C, H, W)    f32  -> 8 MB   (staged in smem, 25x reuse)
// kernel: (N, C*25, H, W) f32  -> 200 MB (dominant HBM stream, read once)
// out:    (N, C, H, W)    f32  -> 8 MB
//
// R2 change: single-wave launch. grid = 512 CTAs (<= 148 SMs * 4 CTA slots),
// each CTA owns 16 consecutive rows of one plane, processed as four 4-row
// tiles. All CTAs do identical work -> zero wave-quantization tail.

#define W_DIM 256
#define H_DIM 256
#define HW (W_DIM * H_DIM)
#define KS 5
#define PAD 2
#define ROWS_PER_TILE 4
#define TILES_PER_CTA 4
#define ROWS_PER_CTA (ROWS_PER_TILE * TILES_PER_CTA)   // 16
#define TILE_ROWS (ROWS_PER_TILE + 2 * PAD)            // 8
#define SROW 264                                       // 256 + 2*PAD, padded

__global__ __launch_bounds__(256, 4)
void dynconv5x5_kernel(const float* __restrict__ x,
                       const float* __restrict__ kern,
                       float* __restrict__ out)
{
    __shared__ float xs[TILE_ROWS][SROW];

    const int nc    = blockIdx.x >> 4;                 // plane index (0..31)
    const int hbase = (blockIdx.x & 15) * ROWS_PER_CTA; // first row of CTA's strip
    const int tid   = threadIdx.y * 64 + threadIdx.x;
    const int tx    = threadIdx.x;                     // 0..63 -> 4-px group
    const int ty    = threadIdx.y;                     // 0..3  -> row in tile
    const int wbase = tx * 4;

    const float* xp    = x    + (size_t)nc * HW;
    const float* kpl   = kern + (size_t)nc * 25 * HW;
    float*       outpl = out  + (size_t)nc * HW;

    #pragma unroll 1
    for (int t = 0; t < TILES_PER_CTA; t++) {
        const int h0 = hbase + t * ROWS_PER_TILE;

        if (t) __syncthreads();   // previous tile's smem reads done before overwrite

        // ---- stage x tile (rows h0-2..h0+5, cols -2..261, replicate clamp) ----
        #pragma unroll
        for (int idx = tid; idx < TILE_ROWS * SROW; idx += 256) {
            int r = idx / SROW;
            int c = idx - r * SROW;
            int gy = h0 + r - PAD;
            gy = gy < 0 ? 0 : (gy > H_DIM - 1 ? H_DIM - 1 : gy);
            int gx = c - PAD;
            gx = gx < 0 ? 0 : (gx > W_DIM - 1 ? W_DIM - 1 : gx);
            xs[r][c] = __ldg(xp + gy * W_DIM + gx);
        }
        __syncthreads();

        const int h = h0 + ty;
        const float* kbase = kpl + (size_t)h * W_DIM + wbase;

        float acc0 = 0.f, acc1 = 0.f, acc2 = 0.f, acc3 = 0.f;

        // Double-buffered tap rows: next row's 5 LDG.128 issued before the
        // current row is consumed -> up to 10 independent loads in flight.
        float4 kv[2][KS];
        #pragma unroll
        for (int k2 = 0; k2 < KS; k2++)
            kv[0][k2] = __ldcs((const float4*)(kbase + (size_t)k2 * HW));

        #pragma unroll
        for (int k1 = 0; k1 < KS; k1++) {
            const int cur = k1 & 1;
            if (k1 < KS - 1) {
                #pragma unroll
                for (int k2 = 0; k2 < KS; k2++)
                    kv[cur ^ 1][k2] =
                        __ldcs((const float4*)(kbase + (size_t)((k1 + 1) * KS + k2) * HW));
            }

            // 8-float sliding window for this tap row (aligned LDS.128 x2)
            float4 a = *(const float4*)&xs[ty + k1][wbase];
            float4 b = *(const float4*)&xs[ty + k1][wbase + 4];
            float r[8] = {a.x, a.y, a.z, a.w, b.x, b.y, b.z, b.w};

            #pragma unroll
            for (int k2 = 0; k2 < KS; k2++) {
                float4 c4 = kv[cur][k2];
                acc0 = fmaf(c4.x, r[k2 + 0], acc0);
                acc1 = fmaf(c4.y, r[k2 + 1], acc1);
                acc2 = fmaf(c4.z, r[k2 + 2], acc2);
                acc3 = fmaf(c4.w, r[k2 + 3], acc3);
            }
        }

        // leaky_relu(0.2)
        acc0 = acc0 >= 0.f ? acc0 : 0.2f * acc0;
        acc1 = acc1 >= 0.f ? acc1 : 0.2f * acc1;
        acc2 = acc2 >= 0.f ? acc2 : 0.2f * acc2;
        acc3 = acc3 >= 0.f ? acc3 : 0.2f * acc3;

        float4 o = make_float4(acc0, acc1, acc2, acc3);
        *(float4*)(outpl + (size_t)h * W_DIM + wbase) = o;
    }
}

extern "C" void kernel_launch(void* const* d_in, const int* in_sizes, int n_in,
                              void* d_out, int out_size)
{
    const float* x    = (const float*)d_in[0];
    const float* kern = (const float*)d_in[1];
    float* out        = (float*)d_out;

    const int NC = in_sizes[0] / HW;              // 32 for (4,8,256,256)

    dim3 block(64, 4);
    dim3 grid(NC * (H_DIM / ROWS_PER_CTA));       // 32 * 16 = 512 CTAs, one wave
    dynconv5x5_kernel<<<grid, block>>>(x, kern, out);
}

// round 5
// speedup vs baseline: 1.0250x; 1.0250x over previous
#include <cuda_runtime.h>

// Dynamic 5x5 per-pixel convolution + leaky_relu(0.2), replicate padding.
// x:      (N, C, H, W)    f32  -> 8 MB   (staged once per CTA, 25x reuse)
// kernel: (N, C*25, H, W) f32  -> 200 MB (dominant HBM stream, read once)
// out:    (N, C, H, W)    f32  -> 8 MB
//
// R3 change: single-wave (512 CTAs) AND zero mid-stream barriers.
// Each CTA stages its full 16-row strip (+halo = 20x264 = 21KB smem) up
// front with ONE sync, then streams all 25*16 tap rows uninterrupted.
// Each thread: 4 rows x 4 px, storing each row when done (4 accs live).

#define W_DIM 256
#define H_DIM 256
#define HW (W_DIM * H_DIM)
#define KS 5
#define PAD 2
#define ROWS_PER_CTA 16
#define ROWS_PER_THREAD 4
#define TILE_ROWS (ROWS_PER_CTA + 2 * PAD)   // 20
#define SROW 264                             // 256 + 2*PAD, padded

__global__ __launch_bounds__(256, 4)
void dynconv5x5_kernel(const float* __restrict__ x,
                       const float* __restrict__ kern,
                       float* __restrict__ out)
{
    __shared__ float xs[TILE_ROWS][SROW];

    const int nc    = blockIdx.x >> 4;                   // plane index (0..31)
    const int hbase = (blockIdx.x & 15) * ROWS_PER_CTA;  // strip start row
    const int tid   = threadIdx.y * 64 + threadIdx.x;
    const int tx    = threadIdx.x;                       // 0..63 -> 4-px group
    const int ty    = threadIdx.y;                       // 0..3
    const int wbase = tx * 4;

    const float* xp    = x    + (size_t)nc * HW;
    const float* kpl   = kern + (size_t)nc * 25 * HW;
    float*       outpl = out  + (size_t)nc * HW;

    // ---- stage full strip + halo once (rows hbase-2..hbase+17, cols -2..261) ----
    for (int idx = tid; idx < TILE_ROWS * SROW; idx += 256) {
        int r = idx / SROW;
        int c = idx - r * SROW;
        int gy = hbase + r - PAD;
        gy = gy < 0 ? 0 : (gy > H_DIM - 1 ? H_DIM - 1 : gy);
        int gx = c - PAD;
        gx = gx < 0 ? 0 : (gx > W_DIM - 1 ? W_DIM - 1 : gx);
        xs[r][c] = __ldg(xp + gy * W_DIM + gx);
    }
    __syncthreads();   // the ONLY barrier — tap stream below never stops

    // Each thread: rows hbase + ty + 4*rr, rr = 0..3
    #pragma unroll 1
    for (int rr = 0; rr < ROWS_PER_THREAD; rr++) {
        const int hloc = ty + rr * 4;            // row within strip (0..15)
        const int h    = hbase + hloc;           // global row
        const float* kbase = kpl + (size_t)h * W_DIM + wbase;

        float acc0 = 0.f, acc1 = 0.f, acc2 = 0.f, acc3 = 0.f;

        // Double-buffered tap rows: next row's 5 LDG.128 in flight while
        // consuming current -> ~10 independent loads outstanding.
        float4 kv[2][KS];
        #pragma unroll
        for (int k2 = 0; k2 < KS; k2++)
            kv[0][k2] = __ldcs((const float4*)(kbase + (size_t)k2 * HW));

        #pragma unroll
        for (int k1 = 0; k1 < KS; k1++) {
            const int cur = k1 & 1;
            if (k1 < KS - 1) {
                #pragma unroll
                for (int k2 = 0; k2 < KS; k2++)
                    kv[cur ^ 1][k2] =
                        __ldcs((const float4*)(kbase + (size_t)((k1 + 1) * KS + k2) * HW));
            }

            // 8-float sliding window from smem (aligned LDS.128 x2)
            float4 a = *(const float4*)&xs[hloc + k1][wbase];
            float4 b = *(const float4*)&xs[hloc + k1][wbase + 4];
            float r[8] = {a.x, a.y, a.z, a.w, b.x, b.y, b.z, b.w};

            #pragma unroll
            for (int k2 = 0; k2 < KS; k2++) {
                float4 c4 = kv[cur][k2];
                acc0 = fmaf(c4.x, r[k2 + 0], acc0);
                acc1 = fmaf(c4.y, r[k2 + 1], acc1);
                acc2 = fmaf(c4.z, r[k2 + 2], acc2);
                acc3 = fmaf(c4.w, r[k2 + 3], acc3);
            }
        }

        // leaky_relu(0.2) + store this row's 4 px immediately
        acc0 = acc0 >= 0.f ? acc0 : 0.2f * acc0;
        acc1 = acc1 >= 0.f ? acc1 : 0.2f * acc1;
        acc2 = acc2 >= 0.f ? acc2 : 0.2f * acc2;
        acc3 = acc3 >= 0.f ? acc3 : 0.2f * acc3;

        *(float4*)(outpl + (size_t)h * W_DIM + wbase) =
            make_float4(acc0, acc1, acc2, acc3);
    }
}

extern "C" void kernel_launch(void* const* d_in, const int* in_sizes, int n_in,
                              void* d_out, int out_size)
{
    const float* x    = (const float*)d_in[0];
    const float* kern = (const float*)d_in[1];
    float* out        = (float*)d_out;

    const int NC = in_sizes[0] / HW;              // 32 for (4,8,256,256)

    dim3 block(64, 4);
    dim3 grid(NC * (H_DIM / ROWS_PER_CTA));       // 32 * 16 = 512 CTAs, one wave
    dynconv5x5_kernel<<<grid, block>>>(x, kern, out);
}

// round 6
// speedup vs baseline: 1.0882x; 1.0616x over previous
#include <cuda_runtime.h>
#include <cstdint>

// Dynamic 5x5 per-pixel convolution + leaky_relu(0.2), replicate padding.
// x:      (N, C, H, W)    f32  -> 8 MB   (staged once per CTA via cp.async)
// kernel: (N, C*25, H, W) f32  -> 200 MB (dominant HBM stream, read once)
// out:    (N, C, H, W)    f32  -> 8 MB
//
// R5: keep R3's single-wave / single-sync structure; remove the two bubbles:
//  - x stage via cp.async (no regs, no LDG-issue blocking)
//  - row-0 tap LDGs issued BEFORE the stage wait -> first-row DRAM latency
//    hidden under the stage
//  - streaming stores

#define W_DIM 256
#define H_DIM 256
#define HW (W_DIM * H_DIM)
#define KS 5
#define PAD 2
#define ROWS_PER_CTA 16
#define ROWS_PER_THREAD 4
#define TILE_ROWS (ROWS_PER_CTA + 2 * PAD)   // 20
#define SROW 264                             // 256 + 2*PAD, padded

__device__ __forceinline__ void cp_async4(uint32_t smem_addr, const float* gptr) {
    asm volatile("cp.async.ca.shared.global [%0], [%1], 4;"
                 :: "r"(smem_addr), "l"(gptr));
}

__global__ __launch_bounds__(256, 4)
void dynconv5x5_kernel(const float* __restrict__ x,
                       const float* __restrict__ kern,
                       float* __restrict__ out)
{
    __shared__ float xs[TILE_ROWS][SROW];

    const int nc    = blockIdx.x >> 4;                   // plane index (0..31)
    const int hbase = (blockIdx.x & 15) * ROWS_PER_CTA;  // strip start row
    const int tid   = threadIdx.y * 64 + threadIdx.x;
    const int tx    = threadIdx.x;                       // 0..63 -> 4-px group
    const int ty    = threadIdx.y;                       // 0..3
    const int wbase = tx * 4;

    const float* xp    = x    + (size_t)nc * HW;
    const float* kpl   = kern + (size_t)nc * 25 * HW;
    float*       outpl = out  + (size_t)nc * HW;

    // ---- stage full strip + halo via cp.async (replicate clamp at fill) ----
    uint32_t xs_base;
    asm("{ .reg .u64 t; cvta.to.shared.u64 t, %1; cvt.u32.u64 %0, t; }"
        : "=r"(xs_base) : "l"(&xs[0][0]));

    for (int idx = tid; idx < TILE_ROWS * SROW; idx += 256) {
        int r = idx / SROW;
        int c = idx - r * SROW;
        int gy = hbase + r - PAD;
        gy = gy < 0 ? 0 : (gy > H_DIM - 1 ? H_DIM - 1 : gy);
        int gx = c - PAD;
        gx = gx < 0 ? 0 : (gx > W_DIM - 1 ? W_DIM - 1 : gx);
        cp_async4(xs_base + (uint32_t)idx * 4u, xp + gy * W_DIM + gx);
    }
    asm volatile("cp.async.commit_group;");

    // ---- prefetch row-0 taps for rr=0 BEFORE the stage wait ----
    float4 kv[2][KS];
    {
        const int h0 = hbase + ty;
        const float* kb0 = kpl + (size_t)h0 * W_DIM + wbase;
        #pragma unroll
        for (int k2 = 0; k2 < KS; k2++)
            kv[0][k2] = __ldcs((const float4*)(kb0 + (size_t)k2 * HW));
    }

    asm volatile("cp.async.wait_group 0;");
    __syncthreads();   // the ONLY barrier

    // Each thread: rows hbase + ty + 4*rr, rr = 0..3
    #pragma unroll 1
    for (int rr = 0; rr < ROWS_PER_THREAD; rr++) {
        const int hloc = ty + rr * 4;            // row within strip (0..15)
        const int h    = hbase + hloc;           // global row
        const float* kbase = kpl + (size_t)h * W_DIM + wbase;

        if (rr > 0) {   // rr=0's kv[0] was preloaded under the stage wait
            #pragma unroll
            for (int k2 = 0; k2 < KS; k2++)
                kv[0][k2] = __ldcs((const float4*)(kbase + (size_t)k2 * HW));
        }

        float acc0 = 0.f, acc1 = 0.f, acc2 = 0.f, acc3 = 0.f;

        #pragma unroll
        for (int k1 = 0; k1 < KS; k1++) {
            const int cur = k1 & 1;
            if (k1 < KS - 1) {
                #pragma unroll
                for (int k2 = 0; k2 < KS; k2++)
                    kv[cur ^ 1][k2] =
                        __ldcs((const float4*)(kbase + (size_t)((k1 + 1) * KS + k2) * HW));
            }

            // 8-float sliding window from smem (aligned LDS.128 x2)
            float4 a = *(const float4*)&xs[hloc + k1][wbase];
            float4 b = *(const float4*)&xs[hloc + k1][wbase + 4];
            float r[8] = {a.x, a.y, a.z, a.w, b.x, b.y, b.z, b.w};

            #pragma unroll
            for (int k2 = 0; k2 < KS; k2++) {
                float4 c4 = kv[cur][k2];
                acc0 = fmaf(c4.x, r[k2 + 0], acc0);
                acc1 = fmaf(c4.y, r[k2 + 1], acc1);
                acc2 = fmaf(c4.z, r[k2 + 2], acc2);
                acc3 = fmaf(c4.w, r[k2 + 3], acc3);
            }
        }

        // leaky_relu(0.2) + streaming store of this row's 4 px
        acc0 = acc0 >= 0.f ? acc0 : 0.2f * acc0;
        acc1 = acc1 >= 0.f ? acc1 : 0.2f * acc1;
        acc2 = acc2 >= 0.f ? acc2 : 0.2f * acc2;
        acc3 = acc3 >= 0.f ? acc3 : 0.2f * acc3;

        __stcs((float4*)(outpl + (size_t)h * W_DIM + wbase),
               make_float4(acc0, acc1, acc2, acc3));
    }
}

extern "C" void kernel_launch(void* const* d_in, const int* in_sizes, int n_in,
                              void* d_out, int out_size)
{
    const float* x    = (const float*)d_in[0];
    const float* kern = (const float*)d_in[1];
    float* out        = (float*)d_out;

    const int NC = in_sizes[0] / HW;              // 32 for (4,8,256,256)

    dim3 block(64, 4);
    dim3 grid(NC * (H_DIM / ROWS_PER_CTA));       // 512 CTAs, single wave
    dynconv5x5_kernel<<<grid, block>>>(x, kern, out);
}